// round 1
// baseline (speedup 1.0000x reference)
#include <cuda_runtime.h>
#include <math.h>

#define NN 8192
#define DDIM 200
#define CAP (1 << 20)

__device__ float g_b[NN];
__device__ float g_e[NN];
__device__ float g_Smax[NN];   // suffix max of e
__device__ double g_sb, g_se;  // sums of expf(b), expf(e)
__device__ float g_T;          // threshold on s = b_i + e_j
__device__ unsigned g_cnt;
__device__ float g_cv[CAP];
__device__ unsigned g_ci[CAP];

__global__ void k_init() {
    g_sb = 0.0;
    g_se = 0.0;
}

// One warp per row: b_i = dot(G[i], wb), e_i = dot(G[i], we); accumulate exp sums.
__global__ void k_dots(const float* __restrict__ G,
                       const float* __restrict__ wb,
                       const float* __restrict__ we) {
    int wib = threadIdx.x >> 5;
    int row = blockIdx.x * 8 + wib;
    int lane = threadIdx.x & 31;
    const float* rp = G + (size_t)row * DDIM;
    float sb = 0.f, se = 0.f;
#pragma unroll
    for (int t = 0; t < 7; t++) {
        int c = lane + 32 * t;
        if (c < DDIM) {
            float g = rp[c];
            sb += g * wb[c];
            se += g * we[c];
        }
    }
#pragma unroll
    for (int o = 16; o; o >>= 1) {
        sb += __shfl_xor_sync(0xffffffffu, sb, o);
        se += __shfl_xor_sync(0xffffffffu, se, o);
    }
    __shared__ double s_eb[8], s_ee[8];
    if (lane == 0) {
        g_b[row] = sb;
        g_e[row] = se;
        s_eb[wib] = (double)expf(sb);
        s_ee[wib] = (double)expf(se);
    }
    __syncthreads();
    if (threadIdx.x == 0) {
        double a = 0.0, b = 0.0;
        for (int w = 0; w < 8; w++) { a += s_eb[w]; b += s_ee[w]; }
        atomicAdd(&g_sb, a);
        atomicAdd(&g_se, b);
    }
}

// Single block: prefix-max(b), c_j = m_j + e_j, kth largest c -> threshold T;
// suffix-max(e) -> g_Smax; reset candidate counter.
__global__ void k_thresh(const int* __restrict__ kp) {
    __shared__ float sm[NN];
    __shared__ float chunk[1024];
    __shared__ float excl[1024];
    __shared__ float rv[32];
    __shared__ int rp[32];
    int tid = threadIdx.x;
    int k = *kp;

    for (int j = tid; j < NN; j += 1024) sm[j] = g_b[j];
    __syncthreads();

    int base = tid * 8;
    // in-place inclusive prefix max within 8-element chunk
    float m = sm[base];
#pragma unroll
    for (int t = 1; t < 8; t++) { m = fmaxf(m, sm[base + t]); sm[base + t] = m; }
    chunk[tid] = m;
    __syncthreads();
    if (tid == 0) {
        float run = -INFINITY;
        for (int t = 0; t < 1024; t++) { excl[t] = run; run = fmaxf(run, chunk[t]); }
    }
    __syncthreads();
    {
        float pre = excl[tid];
#pragma unroll
        for (int t = 0; t < 8; t++)
            sm[base + t] = fmaxf(sm[base + t], pre) + g_e[base + t];
    }
    __syncthreads();

    // k argmax rounds over c (sm) -> T = kth largest
    float T = -INFINITY;
    for (int r = 0; r < k; r++) {
        float bestv = -INFINITY;
        int bestp = 0;
#pragma unroll
        for (int u = 0; u < 8; u++) {
            int j = tid + u * 1024;
            float v = sm[j];
            if (v > bestv) { bestv = v; bestp = j; }
        }
#pragma unroll
        for (int o = 16; o; o >>= 1) {
            float ov = __shfl_xor_sync(0xffffffffu, bestv, o);
            int op = __shfl_xor_sync(0xffffffffu, bestp, o);
            if (ov > bestv || (ov == bestv && op < bestp)) { bestv = ov; bestp = op; }
        }
        if ((tid & 31) == 0) { rv[tid >> 5] = bestv; rp[tid >> 5] = bestp; }
        __syncthreads();
        if (tid < 32) {
            bestv = rv[tid];
            bestp = rp[tid];
#pragma unroll
            for (int o = 16; o; o >>= 1) {
                float ov = __shfl_xor_sync(0xffffffffu, bestv, o);
                int op = __shfl_xor_sync(0xffffffffu, bestp, o);
                if (ov > bestv || (ov == bestv && op < bestp)) { bestv = ov; bestp = op; }
            }
            if (tid == 0) { rv[0] = bestv; rp[0] = bestp; }
        }
        __syncthreads();
        T = rv[0];
        if (tid == 0) sm[rp[0]] = -INFINITY;
        __syncthreads();
    }

    // suffix max of e
    for (int j = tid; j < NN; j += 1024) sm[j] = g_e[j];
    __syncthreads();
    {
        float mm = -INFINITY;
#pragma unroll
        for (int t = 7; t >= 0; t--) { mm = fmaxf(mm, sm[base + t]); sm[base + t] = mm; }
        chunk[tid] = mm;
    }
    __syncthreads();
    if (tid == 0) {
        float run = -INFINITY;
        for (int t = 1023; t >= 0; t--) { excl[t] = run; run = fmaxf(run, chunk[t]); }
    }
    __syncthreads();
    {
        float pre = excl[tid];
#pragma unroll
        for (int t = 0; t < 8; t++)
            g_Smax[base + t] = fmaxf(sm[base + t], pre);
    }
    if (tid == 0) { g_T = T; g_cnt = 0u; }
}

// Collect all pairs (i<=j) with b_i + e_j >= T (relaxed), pruned per-row by suffix-max.
__global__ void k_collect() {
    int gw = (blockIdx.x * blockDim.x + threadIdx.x) >> 5;
    int lane = threadIdx.x & 31;
    int nw = (gridDim.x * blockDim.x) >> 5;
    float T = g_T;
    float Tr = T - (fabsf(T) * 1e-5f + 1e-5f);  // conservative slack for fp rounding
    const float4* e4 = reinterpret_cast<const float4*>(g_e);
    for (int i = gw; i < NN; i += nw) {
        float bi = g_b[i];
        float t = Tr - bi;
        if (g_Smax[i] < t) continue;  // whole row has no candidates
        for (int q = lane; q < NN / 4; q += 32) {
            int j0 = q * 4;
            if (j0 + 3 < i) continue;
            float4 ev = e4[q];
            float mx = fmaxf(fmaxf(ev.x, ev.y), fmaxf(ev.z, ev.w));
            if (mx < t) continue;
            float es[4] = {ev.x, ev.y, ev.z, ev.w};
#pragma unroll
            for (int u = 0; u < 4; u++) {
                int j = j0 + u;
                if (j >= i && es[u] >= t) {
                    float s = bi + es[u];
                    unsigned pos = atomicAdd(&g_cnt, 1u);
                    if (pos < CAP) {
                        g_cv[pos] = s;
                        g_ci[pos] = (unsigned)i * NN + (unsigned)j;
                    }
                }
            }
        }
    }
}

// Single block: exact top-k over candidates by (expf(s) desc, flat idx asc), write output.
__global__ void k_final(const int* __restrict__ kp, float* __restrict__ out, int out_size) {
    __shared__ unsigned long long skey[32];
    __shared__ int spos[32];
    int tid = threadIdx.x;
    int k = *kp;
    unsigned M = g_cnt;
    if (M > (unsigned)CAP) M = (unsigned)CAP;
    float denom = (float)(g_sb * g_se);

    // precompute numerator v = expf(s) in place (matches reference's f32 exp ordering)
    for (unsigned c = tid; c < M; c += blockDim.x) g_cv[c] = expf(g_cv[c]);
    __syncthreads();

    for (int r = 0; r < k; r++) {
        unsigned long long bk = 0ull;
        int bp = -1;
        for (unsigned c = tid; c < M; c += blockDim.x) {
            float v = g_cv[c];
            if (v > 0.f) {
                unsigned long long key =
                    ((unsigned long long)__float_as_uint(v) << 32) |
                    (unsigned long long)(0xFFFFFFFFu - g_ci[c]);
                if (key > bk) { bk = key; bp = (int)c; }
            }
        }
#pragma unroll
        for (int o = 16; o; o >>= 1) {
            unsigned long long ok = __shfl_xor_sync(0xffffffffu, bk, o);
            int op = __shfl_xor_sync(0xffffffffu, bp, o);
            if (ok > bk) { bk = ok; bp = op; }
        }
        if ((tid & 31) == 0) { skey[tid >> 5] = bk; spos[tid >> 5] = bp; }
        __syncthreads();
        if (tid < 32) {
            bk = skey[tid];
            bp = spos[tid];
#pragma unroll
            for (int o = 16; o; o >>= 1) {
                unsigned long long ok = __shfl_xor_sync(0xffffffffu, bk, o);
                int op = __shfl_xor_sync(0xffffffffu, bp, o);
                if (ok > bk) { bk = ok; bp = op; }
            }
            if (tid == 0 && bp >= 0) {
                unsigned idx = g_ci[bp];
                unsigned ii = idx / NN;
                unsigned jj = idx % NN;
                float v = g_cv[bp];
                if (2 * r + 1 < out_size) {
                    out[2 * r] = (float)ii;
                    out[2 * r + 1] = (float)jj;
                }
                if (2 * k + r < out_size) out[2 * k + r] = v / denom;
                g_cv[bp] = 0.f;  // mark consumed
            }
        }
        __syncthreads();
    }
    // zero any remainder of the output buffer (it is poisoned before timing)
    for (int c = 3 * k + tid; c < out_size; c += blockDim.x) out[c] = 0.f;
}

extern "C" void kernel_launch(void* const* d_in, const int* in_sizes, int n_in,
                              void* d_out, int out_size) {
    const float* G = (const float*)d_in[0];
    const float* wb = (const float*)d_in[1];
    const float* we = (const float*)d_in[2];
    const int* kp = (const int*)d_in[3];
    float* out = (float*)d_out;

    k_init<<<1, 1>>>();
    k_dots<<<NN / 8, 256>>>(G, wb, we);
    k_thresh<<<1, 1024>>>(kp);
    k_collect<<<592, 256>>>();
    k_final<<<1, 1024>>>(kp, out, out_size);
}

// round 2
// speedup vs baseline: 3.9115x; 3.9115x over previous
#include <cuda_runtime.h>
#include <math.h>

#define NN 8192
#define DDIM 200
#define NB_DOTS 256        // k_dots blocks (32 rows each)
#define CAP (1 << 18)      // candidate cap
#define KMAX 128

__device__ float g_b[NN];
__device__ float g_e[NN];
__device__ double g_pb[NB_DOTS], g_pe[NB_DOTS];
__device__ int   g_Ri[NN];
__device__ float g_Rb[NN];
__device__ int   g_Jj[NN];
__device__ float g_Je[NN];
__device__ unsigned long long g_keys[CAP];

// ---------- GEMV: warp per row, per-block partial exp-sums ----------
__global__ void __launch_bounds__(1024) k_dots(const float* __restrict__ G,
                                               const float* __restrict__ wb,
                                               const float* __restrict__ we) {
    int wib = threadIdx.x >> 5;
    int lane = threadIdx.x & 31;
    int row = blockIdx.x * 32 + wib;
    const float* rp = G + (size_t)row * DDIM;
    float sbv = 0.f, sev = 0.f;
#pragma unroll
    for (int t = 0; t < 7; t++) {
        int c = lane + 32 * t;
        if (c < DDIM) {
            float g = rp[c];
            sbv += g * wb[c];
            sev += g * we[c];
        }
    }
#pragma unroll
    for (int o = 16; o; o >>= 1) {
        sbv += __shfl_xor_sync(0xffffffffu, sbv, o);
        sev += __shfl_xor_sync(0xffffffffu, sev, o);
    }
    __shared__ double eb[32], ee[32];
    if (lane == 0) {
        g_b[row] = sbv;
        g_e[row] = sev;
        eb[wib] = (double)expf(sbv);
        ee[wib] = (double)expf(sev);
    }
    __syncthreads();
    if (threadIdx.x == 0) {
        double a = 0.0, b = 0.0;
#pragma unroll
        for (int w = 0; w < 32; w++) { a += eb[w]; b += ee[w]; }
        g_pb[blockIdx.x] = a;
        g_pe[blockIdx.x] = b;
    }
}

__device__ __forceinline__ unsigned f2u(float x) {
    unsigned u = __float_as_uint(x);
    return (u & 0x80000000u) ? ~u : (u | 0x80000000u);
}
__device__ __forceinline__ float u2f(unsigned u) {
    unsigned v = (u & 0x80000000u) ? (u & 0x7FFFFFFFu) : ~u;
    return __uint_as_float(v);
}

// ---------- Everything else in one block ----------
__global__ void __launch_bounds__(1024) k_master(const int* __restrict__ kp,
                                                 float* __restrict__ out,
                                                 int out_size) {
    __shared__ float buf[NN];          // 32KB
    __shared__ float chunkv[1024];     // 4KB
    __shared__ double sred[256];       // 2KB
    __shared__ unsigned hist[256];
    __shared__ unsigned long long s_kpref;
    __shared__ int s_kk;
    __shared__ int s_nR, s_nJ;
    __shared__ unsigned s_m;
    __shared__ float s_denom;
    __shared__ unsigned long long stop[KMAX];   // 1KB
    __shared__ int s_cnt;

    int tid = threadIdx.x;
    int k = *kp;
    if (k < 1) k = 1;
    if (k > KMAX) k = KMAX;
    int base = tid * 8;

    // --- denominator: reduce per-block partials ---
    if (tid < 256) sred[tid] = g_pb[tid];
    __syncthreads();
    for (int off = 128; off; off >>= 1) {
        if (tid < off) sred[tid] += sred[tid + off];
        __syncthreads();
    }
    double sb_sum = sred[0];
    __syncthreads();
    if (tid < 256) sred[tid] = g_pe[tid];
    __syncthreads();
    for (int off = 128; off; off >>= 1) {
        if (tid < off) sred[tid] += sred[tid + off];
        __syncthreads();
    }
    if (tid == 0) {
        s_denom = (float)(sb_sum * sred[0]);
        s_nR = 0; s_nJ = 0; s_m = 0;
    }

    // --- prefix-max(b), c_j = m_j + e_j into buf ---
    float pl[8];
    {
        float run = -INFINITY;
#pragma unroll
        for (int t = 0; t < 8; t++) {
            float v = g_b[base + t];
            run = fmaxf(run, v);
            pl[t] = run;
        }
        chunkv[tid] = run;
    }
    __syncthreads();
    for (int off = 1; off < 1024; off <<= 1) {
        float cur = chunkv[tid];
        float o = (tid >= off) ? chunkv[tid - off] : -INFINITY;
        __syncthreads();
        chunkv[tid] = fmaxf(cur, o);
        __syncthreads();
    }
    {
        float ex = (tid > 0) ? chunkv[tid - 1] : -INFINITY;
#pragma unroll
        for (int t = 0; t < 8; t++)
            buf[base + t] = fmaxf(pl[t], ex) + g_e[base + t];
    }
    __syncthreads();

    // --- radix-select: k-th largest of c (32-bit float keys) ---
    unsigned pref32 = 0;
    {
        int kk = k;
#pragma unroll
        for (int pass = 0; pass < 4; pass++) {
            int shift = 24 - 8 * pass;
            if (tid < 256) hist[tid] = 0u;
            __syncthreads();
            for (int idx = tid; idx < NN; idx += 1024) {
                unsigned u = f2u(buf[idx]);
                if (pass == 0 || (u >> (shift + 8)) == pref32)
                    atomicAdd(&hist[(u >> shift) & 255u], 1u);
            }
            __syncthreads();
            if (tid == 0) {
                int c = 0;
                for (int b = 255; b >= 0; b--) {
                    int h = (int)hist[b];
                    if (c + h >= kk) {
                        s_kpref = ((unsigned long long)pref32 << 8) | (unsigned)b;
                        s_kk = kk - c;
                        break;
                    }
                    c += h;
                }
            }
            __syncthreads();
            pref32 = (unsigned)s_kpref;
            kk = s_kk;
            __syncthreads();
        }
    }
    float T = u2f(pref32);
    float Tr = T - (fabsf(T) * 1e-6f + 1e-6f);

    // --- build J list from c (still in buf) ---
    for (int idx = tid; idx < NN; idx += 1024) {
        if (buf[idx] >= Tr) {
            int p = atomicAdd(&s_nJ, 1);
            g_Jj[p] = idx;
            g_Je[p] = g_e[idx];
        }
    }
    __syncthreads();

    // --- suffix-max(e) + build R list ---
    float sl[8];
    {
        float run = -INFINITY;
#pragma unroll
        for (int t = 7; t >= 0; t--) {
            float v = g_e[base + t];
            run = fmaxf(run, v);
            sl[t] = run;
        }
        chunkv[tid] = run;
    }
    __syncthreads();
    for (int off = 1; off < 1024; off <<= 1) {
        float cur = chunkv[tid];
        float o = (tid + off < 1024) ? chunkv[tid + off] : -INFINITY;
        __syncthreads();
        chunkv[tid] = fmaxf(cur, o);
        __syncthreads();
    }
    {
        float ex = (tid < 1023) ? chunkv[tid + 1] : -INFINITY;
#pragma unroll
        for (int t = 0; t < 8; t++) {
            float smax = fmaxf(sl[t], ex);
            int i = base + t;
            float bi = g_b[i];
            if (bi + smax >= Tr) {
                int p = atomicAdd(&s_nR, 1);
                g_Ri[p] = i;
                g_Rb[p] = bi;
            }
        }
    }
    __syncthreads();

    // --- enumerate R x J candidate pairs ---
    int nR = s_nR, nJ = s_nJ;
    long long total = (long long)nR * (long long)nJ;
    for (long long t = tid; t < total; t += 1024) {
        int r = (int)(t / nJ);
        int q = (int)(t % nJ);
        int i = g_Ri[r];
        int j = g_Jj[q];
        if (j < i) continue;
        float s = g_Rb[r] + g_Je[q];
        if (s >= Tr) {
            unsigned p = atomicAdd(&s_m, 1u);
            if (p < CAP) {
                float v = expf(s);
                unsigned fl = (unsigned)i * NN + (unsigned)j;
                g_keys[p] = ((unsigned long long)__float_as_uint(v) << 32) |
                            (unsigned long long)(0xFFFFFFFFu - fl);
            }
        }
    }
    __syncthreads();
    unsigned M = s_m;
    if (M > (unsigned)CAP) M = (unsigned)CAP;

    // --- radix-select: k-th largest 64-bit key among M candidates ---
    unsigned long long kpref = 0ull;
    {
        int kk = k;
#pragma unroll
        for (int pass = 0; pass < 8; pass++) {
            int shift = 56 - 8 * pass;
            if (tid < 256) hist[tid] = 0u;
            __syncthreads();
            for (unsigned c = tid; c < M; c += 1024) {
                unsigned long long key = g_keys[c];
                if (pass == 0 || (key >> (shift + 8)) == kpref)
                    atomicAdd(&hist[(unsigned)((key >> shift) & 255ull)], 1u);
            }
            __syncthreads();
            if (tid == 0) {
                int c = 0;
                for (int b = 255; b >= 0; b--) {
                    int h = (int)hist[b];
                    if (c + h >= kk) {
                        s_kpref = (kpref << 8) | (unsigned long long)b;
                        s_kk = kk - c;
                        break;
                    }
                    c += h;
                }
                s_cnt = 0;
            }
            __syncthreads();
            kpref = s_kpref;
            kk = s_kk;
            __syncthreads();
        }
    }

    // --- gather the k winners (keys are unique: distinct flat indices) ---
    for (unsigned c = tid; c < M; c += 1024) {
        unsigned long long key = g_keys[c];
        if (key >= kpref) {
            int p = atomicAdd(&s_cnt, 1);
            if (p < KMAX) stop[p] = key;
        }
    }
    __syncthreads();
    int kv = s_cnt;
    if (kv > k) kv = k;

    // --- rank sort (O(k^2)) + write output ---
    float denom = s_denom;
    if (tid < kv) {
        unsigned long long mykey = stop[tid];
        int rank = 0;
        for (int u = 0; u < kv; u++) rank += (stop[u] > mykey);
        unsigned fl = 0xFFFFFFFFu - (unsigned)(mykey & 0xFFFFFFFFull);
        unsigned ii = fl / NN, jj = fl % NN;
        float v = __uint_as_float((unsigned)(mykey >> 32));
        if (2 * rank + 1 < out_size) {
            out[2 * rank] = (float)ii;
            out[2 * rank + 1] = (float)jj;
        }
        if (2 * k + rank < out_size) out[2 * k + rank] = v / denom;
    }
    for (int c = 3 * k + tid; c < out_size; c += 1024) out[c] = 0.f;
}

extern "C" void kernel_launch(void* const* d_in, const int* in_sizes, int n_in,
                              void* d_out, int out_size) {
    const float* G = (const float*)d_in[0];
    const float* wb = (const float*)d_in[1];
    const float* we = (const float*)d_in[2];
    const int* kp = (const int*)d_in[3];
    float* out = (float*)d_out;

    k_dots<<<NB_DOTS, 1024>>>(G, wb, we);
    k_master<<<1, 1024>>>(kp, out, out_size);
}

// round 3
// speedup vs baseline: 7.0925x; 1.8132x over previous
#include <cuda_runtime.h>
#include <math.h>

#define NN 8192
#define DDIM 200
#define NB 256
#define CAP (1 << 18)
#define KMAX 128

__device__ float g_b[NN], g_e[NN];
__device__ double g_pb[NB], g_pe[NB];
__device__ int g_Ri[NN];
__device__ float g_Rb[NN];
__device__ int g_Jj[NN];
__device__ float g_Je[NN];
__device__ unsigned long long g_keys[CAP];

// ---------- GEMV: warp per row ----------
__global__ void __launch_bounds__(1024) k_dots(const float* __restrict__ G,
                                               const float* __restrict__ wb,
                                               const float* __restrict__ we) {
    int wib = threadIdx.x >> 5;
    int lane = threadIdx.x & 31;
    int row = blockIdx.x * 32 + wib;
    const float* rp = G + (size_t)row * DDIM;
    float sbv = 0.f, sev = 0.f;
#pragma unroll
    for (int t = 0; t < 7; t++) {
        int c = lane + 32 * t;
        if (c < DDIM) {
            float g = rp[c];
            sbv += g * wb[c];
            sev += g * we[c];
        }
    }
#pragma unroll
    for (int o = 16; o; o >>= 1) {
        sbv += __shfl_xor_sync(0xffffffffu, sbv, o);
        sev += __shfl_xor_sync(0xffffffffu, sev, o);
    }
    __shared__ double eb[32], ee[32];
    if (lane == 0) {
        g_b[row] = sbv;
        g_e[row] = sev;
        eb[wib] = (double)expf(sbv);
        ee[wib] = (double)expf(sev);
    }
    __syncthreads();
    if (threadIdx.x == 0) {
        double a = 0.0, b = 0.0;
#pragma unroll
        for (int w = 0; w < 32; w++) { a += eb[w]; b += ee[w]; }
        g_pb[blockIdx.x] = a;
        g_pe[blockIdx.x] = b;
    }
}

__device__ __forceinline__ unsigned f2u(float x) {
    unsigned u = __float_as_uint(x);
    return (u & 0x80000000u) ? ~u : (u | 0x80000000u);
}
__device__ __forceinline__ float u2f(unsigned u) {
    unsigned v = (u & 0x80000000u) ? (u & 0x7FFFFFFFu) : ~u;
    return __uint_as_float(v);
}

// one-warp bin-find over hist[256], descending. Writes s_kprefLo (selected byte),
// s_kk (rank within bin), s_binc (bin count). Caller holds prior prefix.
#define BIN_FIND(kk_in)                                                          \
    do {                                                                         \
        unsigned lh[8];                                                          \
        int ls = 0;                                                              \
        _Pragma("unroll") for (int t = 0; t < 8; t++) {                          \
            lh[t] = hist[tid * 8 + t];                                           \
            ls += (int)lh[t];                                                    \
        }                                                                        \
        int suf = ls;                                                            \
        _Pragma("unroll") for (int o = 1; o < 32; o <<= 1) {                     \
            int u = __shfl_down_sync(0xffffffffu, suf, o);                       \
            if (tid + o < 32) suf += u;                                          \
        }                                                                        \
        int above = suf - ls;                                                    \
        int runc = above;                                                        \
        _Pragma("unroll") for (int t = 7; t >= 0; t--) {                         \
            if ((kk_in) > runc && (kk_in) <= runc + (int)lh[t]) {                \
                s_kbyte = (unsigned)(tid * 8 + t);                               \
                s_kk = (kk_in)-runc;                                             \
                s_binc = (int)lh[t];                                             \
            }                                                                    \
            runc += (int)lh[t];                                                  \
        }                                                                        \
    } while (0)

__global__ void __launch_bounds__(1024) k_master(const int* __restrict__ kp,
                                                 float* __restrict__ out,
                                                 int out_size) {
    __shared__ float buf[NN];            // 32KB: c_j values
    __shared__ float wtot[32], wexcl[32];
    __shared__ unsigned hist[256];
    __shared__ double sda[8], sdb[8];
    __shared__ float s_denom;
    __shared__ unsigned s_kbyte;
    __shared__ int s_kk, s_binc;
    __shared__ unsigned long long s_kth;
    __shared__ int s_nR, s_nJ, s_cnt;
    __shared__ unsigned s_m;
    __shared__ unsigned long long stop[KMAX];

    int tid = threadIdx.x;
    int lane = tid & 31;
    int wid = tid >> 5;
    int k = *kp;
    if (k < 1) k = 1;
    if (k > KMAX) k = KMAX;
    int base = tid * 8;

    if (tid == 0) { s_nR = 0; s_nJ = 0; s_m = 0; s_cnt = 0; }

    // ---- denominator: warp-shfl reduce of 2x256 partials ----
    {
        double dv = 0.0;
        if (tid < 256) dv = g_pb[tid];
        else if (tid < 512) dv = g_pe[tid - 256];
#pragma unroll
        for (int o = 16; o; o >>= 1) dv += __shfl_down_sync(0xffffffffu, dv, o);
        if (lane == 0 && wid < 16) {
            if (wid < 8) sda[wid] = dv; else sdb[wid - 8] = dv;
        }
    }

    // ---- prefix-max(b): local + warp shfl + cross-warp ----
    float pl[8];
    float lex;
    {
        float run = -INFINITY;
#pragma unroll
        for (int t = 0; t < 8; t++) {
            run = fmaxf(run, g_b[base + t]);
            pl[t] = run;
        }
        float incl = run;
#pragma unroll
        for (int o = 1; o < 32; o <<= 1) {
            float u = __shfl_up_sync(0xffffffffu, incl, o);
            if (lane >= o) incl = fmaxf(incl, u);
        }
        if (lane == 31) wtot[wid] = incl;
        lex = __shfl_up_sync(0xffffffffu, incl, 1);
        if (lane == 0) lex = -INFINITY;
    }
    __syncthreads();
    if (tid < 32) {
        float v = wtot[tid];
        float incl = v;
#pragma unroll
        for (int o = 1; o < 32; o <<= 1) {
            float u = __shfl_up_sync(0xffffffffu, incl, o);
            if (tid >= o) incl = fmaxf(incl, u);
        }
        float ex = __shfl_up_sync(0xffffffffu, incl, 1);
        if (tid == 0) ex = -INFINITY;
        wexcl[tid] = ex;
    }
    __syncthreads();
    {
        float ex = fmaxf(wexcl[wid], lex);
#pragma unroll
        for (int t = 0; t < 8; t++)
            buf[base + t] = fmaxf(pl[t], ex) + g_e[base + t];
    }
    if (tid == 0) {
        double a = 0.0, b2 = 0.0;
#pragma unroll
        for (int w = 0; w < 8; w++) { a += sda[w]; b2 += sdb[w]; }
        s_denom = (float)(a * b2);
    }
    __syncthreads();

    // ---- select-1: truncated 2-pass radix on c (16 high bits) ----
    unsigned pref = 0;
    {
        int kk = k;
#pragma unroll
        for (int pass = 0; pass < 2; pass++) {
            int shift = 24 - 8 * pass;
            if (tid < 256) hist[tid] = 0u;
            __syncthreads();
#pragma unroll
            for (int it = 0; it < 8; it++) {
                int idx = tid + it * 1024;
                unsigned u = f2u(buf[idx]);
                bool ok = (pass == 0) || ((u >> (shift + 8)) == pref);
                int binx = ok ? (int)((u >> shift) & 255u) : (0x100 + lane);
                unsigned m = __match_any_sync(0xffffffffu, binx);
                if (ok && ((int)(__ffs(m) - 1) == lane))
                    atomicAdd(&hist[binx], (unsigned)__popc(m));
            }
            __syncthreads();
            if (tid < 32) BIN_FIND(kk);
            __syncthreads();
            pref = (pref << 8) | s_kbyte;
            kk = s_kk;
        }
    }
    float T = u2f(pref << 16);
    float Tr = T - (fabsf(T) * 1e-6f + 1e-6f);

    // ---- build J list (columns with c_j >= Tr) ----
#pragma unroll
    for (int it = 0; it < 8; it++) {
        int idx = tid + it * 1024;
        if (buf[idx] >= Tr) {
            int p = atomicAdd(&s_nJ, 1);
            g_Jj[p] = idx;
            g_Je[p] = g_e[idx];
        }
    }

    // ---- suffix-max(e) + build R list ----
    {
        float sl[8];
        float run = -INFINITY;
#pragma unroll
        for (int t = 7; t >= 0; t--) {
            run = fmaxf(run, g_e[base + t]);
            sl[t] = run;
        }
        float incl = run;
#pragma unroll
        for (int o = 1; o < 32; o <<= 1) {
            float u = __shfl_down_sync(0xffffffffu, incl, o);
            if (lane + o < 32) incl = fmaxf(incl, u);
        }
        if (lane == 0) wtot[wid] = incl;
        float lex2 = __shfl_down_sync(0xffffffffu, incl, 1);
        if (lane == 31) lex2 = -INFINITY;
        __syncthreads();
        if (tid < 32) {
            float v = wtot[tid];
            float incl2 = v;
#pragma unroll
            for (int o = 1; o < 32; o <<= 1) {
                float u = __shfl_down_sync(0xffffffffu, incl2, o);
                if (tid + o < 32) incl2 = fmaxf(incl2, u);
            }
            float ex = __shfl_down_sync(0xffffffffu, incl2, 1);
            if (tid == 31) ex = -INFINITY;
            wexcl[tid] = ex;
        }
        __syncthreads();
        float ex = fmaxf(wexcl[wid], lex2);
#pragma unroll
        for (int t = 0; t < 8; t++) {
            float smax = fmaxf(sl[t], ex);
            int i = base + t;
            float bi = g_b[i];
            if (bi + smax >= Tr) {
                int p = atomicAdd(&s_nR, 1);
                g_Ri[p] = i;
                g_Rb[p] = bi;
            }
        }
    }
    __syncthreads();

    // ---- enumerate R x J (warp per row) ----
    {
        int nR = s_nR, nJ = s_nJ;
        for (int r = wid; r < nR; r += 32) {
            int i = g_Ri[r];
            float bi = g_Rb[r];
            float t2 = Tr - bi;
            for (int q = lane; q < nJ; q += 32) {
                int j = g_Jj[q];
                float ej = g_Je[q];
                if (j >= i && ej >= t2) {
                    float v = expf(bi + ej);
                    unsigned fl = (unsigned)i * NN + (unsigned)j;
                    unsigned p = atomicAdd(&s_m, 1u);
                    if (p < CAP)
                        g_keys[p] = ((unsigned long long)__float_as_uint(v) << 32) |
                                    (unsigned long long)(0xFFFFFFFFu - fl);
                }
            }
        }
    }
    __syncthreads();
    unsigned M = s_m;
    if (M > (unsigned)CAP) M = (unsigned)CAP;

    // ---- select-2: radix on 64-bit keys with early exit (keys distinct) ----
    {
        unsigned long long pref64 = 0ull;
        int kk = k;
        int fshift = 0;
        for (int pass = 0; pass < 8; pass++) {
            int shift = 56 - 8 * pass;
            if (tid < 256) hist[tid] = 0u;
            __syncthreads();
            for (unsigned c = tid; c < M; c += 1024) {
                unsigned long long key = g_keys[c];
                bool ok = (pass == 0) || ((key >> (shift + 8)) == pref64);
                unsigned act = __activemask();
                int binx = ok ? (int)((key >> shift) & 255ull) : (0x100 + lane);
                unsigned m = __match_any_sync(act, binx);
                if (ok && ((int)(__ffs(m) - 1) == lane))
                    atomicAdd(&hist[binx], (unsigned)__popc(m));
            }
            __syncthreads();
            if (tid < 32) BIN_FIND(kk);
            __syncthreads();
            pref64 = (pref64 << 8) | (unsigned long long)s_kbyte;
            kk = s_kk;
            fshift = shift;
            if (s_binc == 1) break;
            __syncthreads();
        }
        // retrieve the unique k-th key matching pref64 at fshift
        for (unsigned c = tid; c < M; c += 1024) {
            unsigned long long key = g_keys[c];
            if ((key >> fshift) == pref64) s_kth = key;
        }
    }
    __syncthreads();

    // ---- gather exactly k winners (keys >= kth; all distinct) ----
    {
        unsigned long long kth = s_kth;
        for (unsigned c = tid; c < M; c += 1024) {
            unsigned long long key = g_keys[c];
            if (key >= kth) {
                int p = atomicAdd(&s_cnt, 1);
                if (p < KMAX) stop[p] = key;
            }
        }
    }
    __syncthreads();
    int kv = s_cnt;
    if (kv > k) kv = k;
    if (kv > KMAX) kv = KMAX;

    // ---- rank sort + output ----
    float denom = s_denom;
    if (tid < kv) {
        unsigned long long mykey = stop[tid];
        int rank = 0;
        for (int u = 0; u < kv; u++) rank += (stop[u] > mykey);
        if (rank < k) {
            unsigned fl = 0xFFFFFFFFu - (unsigned)(mykey & 0xFFFFFFFFull);
            unsigned ii = fl / NN, jj = fl % NN;
            float v = __uint_as_float((unsigned)(mykey >> 32));
            if (2 * rank + 1 < out_size) {
                out[2 * rank] = (float)ii;
                out[2 * rank + 1] = (float)jj;
            }
            if (2 * k + rank < out_size) out[2 * k + rank] = v / denom;
        }
    }
    for (int c = 3 * k + tid; c < out_size; c += 1024) out[c] = 0.f;
}

extern "C" void kernel_launch(void* const* d_in, const int* in_sizes, int n_in,
                              void* d_out, int out_size) {
    const float* G = (const float*)d_in[0];
    const float* wb = (const float*)d_in[1];
    const float* we = (const float*)d_in[2];
    const int* kp = (const int*)d_in[3];
    float* out = (float*)d_out;

    k_dots<<<NB, 1024>>>(G, wb, we);
    k_master<<<1, 1024>>>(kp, out, out_size);
}